// round 13
// baseline (speedup 1.0000x reference)
#include <cuda_runtime.h>
#include <math.h>

#define NT_L 512
#define NT_D 256
#define RPB 8
#define NBLK 128
#define KC 32
#define KCBYTES (KC * 512 * 4)

typedef unsigned long long ull;

// ---------------- device scratch ----------------
// Interleaved gate layout: column c = 4*u + gate, gate in {i,f,g,o}
__device__ float g_W0cat[152 * 512];   // [k][c]: k 0..23 from W_ih0, 24..151 from W_hh0
__device__ float g_W1cat[256 * 512];   // [k][c]: k 0..127 from W_ih1, 128..255 from W_hh1
__device__ float g_b0[512];            // interleaved
__device__ float g_b1[512];            // interleaved
__device__ float g_W1T[184 * 128];     // [k][u]  (diffusion)
__device__ float g_W2s[128 * 128];     // [u][v] = W2[v][u]
__device__ float g_A1t[100 * 128];
__device__ float g_cy[100];
__device__ float g_ce[100];
__device__ float g_enc[1024 * 128];    // enc_out handoff: [block][128 u][8 r]

// ---------------- prologue ----------------
__global__ void prologue_kernel(const float* __restrict__ W_ih0, const float* __restrict__ W_hh0,
                                const float* __restrict__ b_ih0, const float* __restrict__ b_hh0,
                                const float* __restrict__ W_ih1, const float* __restrict__ W_hh1,
                                const float* __restrict__ b_ih1, const float* __restrict__ b_hh1,
                                const float* __restrict__ W1,    const float* __restrict__ W2) {
    int tid = blockIdx.x * blockDim.x + threadIdx.x;
    int nth = gridDim.x * blockDim.x;

    for (int i = tid; i < 152 * 512; i += nth) {
        int k = i >> 9, c = i & 511;
        int u = c >> 2, gi = c & 3;
        int row = gi * 128 + u;
        g_W0cat[i] = (k < 24) ? W_ih0[row * 24 + k] : W_hh0[row * 128 + (k - 24)];
    }
    for (int i = tid; i < 256 * 512; i += nth) {
        int k = i >> 9, c = i & 511;
        int u = c >> 2, gi = c & 3;
        int row = gi * 128 + u;
        g_W1cat[i] = (k < 128) ? W_ih1[row * 128 + k] : W_hh1[row * 128 + (k - 128)];
    }
    for (int i = tid; i < 512; i += nth) {
        int u = i >> 2, gi = i & 3;
        int row = gi * 128 + u;
        g_b0[i] = b_ih0[row] + b_hh0[row];
        g_b1[i] = b_ih1[row] + b_hh1[row];
    }
    for (int i = tid; i < 184 * 128; i += nth) {
        int k = i >> 7, u = i & 127;
        g_W1T[i] = W1[u * 184 + k];
    }
    for (int i = tid; i < 128 * 128; i += nth) {
        int u = i >> 7, v = i & 127;
        g_W2s[i] = W2[v * 128 + u];
    }
    for (int i = tid; i < 100 * 128; i += nth) {
        int t = i >> 7, u = i & 127;
        float acc = 0.f;
        #pragma unroll
        for (int j = 0; j < 8; j++) {
            float f = expf(-logf(10000.0f) * (float)j / 8.0f);
            float a = (float)t * f;
            acc += W1[u * 184 + 152 + j] * cosf(a);
            acc += W1[u * 184 + 160 + j] * sinf(a);
        }
        g_A1t[i] = acc;
    }
    if (tid == 0) {
        float ab = 1.0f;
        for (int t = 0; t < 100; t++) {
            float beta  = 1e-4f + (0.02f - 1e-4f) * (float)t / 99.0f;
            float alpha = 1.0f - beta;
            ab *= alpha;
            if (t == 0) {
                float p = sqrtf(ab) + 1e-8f;
                g_cy[0] = 1.0f / p;
                g_ce[0] = sqrtf(1.0f - ab) / p;
            } else {
                float inv = 1.0f / (sqrtf(alpha) + 1e-8f);
                g_cy[t] = inv;
                g_ce[t] = beta / (sqrtf(1.0f - ab) + 1e-8f) * inv;
            }
        }
    }
}

// ---------------- fast math helpers ----------------
__device__ __forceinline__ float sigf(float x) {
    float xc = fminf(fmaxf(x, -30.f), 30.f);
    return __fdividef(1.0f, 1.0f + __expf(-xc));
}
__device__ __forceinline__ float tanhf_fast(float x) {
    float xc = fminf(fmaxf(x, -15.f), 15.f);
    float e = __expf(2.0f * xc);
    return __fdividef(e - 1.0f, e + 1.0f);
}
__device__ __forceinline__ void ffma2(ull &d, ull a, ull b) {
    asm("fma.rn.f32x2 %0, %1, %2, %0;" : "+l"(d) : "l"(a), "l"(b));
}
__device__ __forceinline__ void fadd2(ull &d, ull a) {
    asm("add.rn.f32x2 %0, %0, %1;" : "+l"(d) : "l"(a));
}
__device__ __forceinline__ ull dup2(float x) {
    ull r;
    asm("mov.b64 %0, {%1, %1};" : "=l"(r) : "f"(x));
    return r;
}
__device__ __forceinline__ ull pack2(float lo, float hi) {
    ull r;
    asm("mov.b64 %0, {%1, %2};" : "=l"(r) : "f"(lo), "f"(hi));
    return r;
}
__device__ __forceinline__ float2 unpack2(ull v) {
    float2 r;
    asm("mov.b64 {%0, %1}, %2;" : "=f"(r.x), "=f"(r.y) : "l"(v));
    return r;
}
__device__ __forceinline__ unsigned smem_u32(const void* p) {
    unsigned a;
    asm("{ .reg .u64 t; cvta.to.shared.u64 t, %1; cvt.u32.u64 %0, t; }" : "=r"(a) : "l"(p));
    return a;
}

// ---------------- bulk staging (TMA path) ----------------
__device__ __forceinline__ void bulk_stage(unsigned dst, const float* __restrict__ src,
                                           unsigned bytes, unsigned mbar) {
    asm volatile("mbarrier.arrive.expect_tx.shared.b64 _, [%0], %1;"
                 :: "r"(mbar), "r"(bytes) : "memory");
    asm volatile("cp.async.bulk.shared::cluster.global.mbarrier::complete_tx::bytes [%0], [%1], %2, [%3];"
                 :: "r"(dst), "l"(src), "r"(bytes), "r"(mbar) : "memory");
}
__device__ __forceinline__ void mbar_wait(unsigned mbar, int phase) {
    asm volatile(
        "{\n\t.reg .pred P1;\n\t"
        "WAIT_LOOP_%=:\n\t"
        "mbarrier.try_wait.parity.shared.b64 P1, [%0], %1;\n\t"
        "@P1 bra.uni WAIT_DONE_%=;\n\t"
        "bra.uni WAIT_LOOP_%=;\n\t"
        "WAIT_DONE_%=:\n\t}"
        :: "r"(mbar), "r"(phase) : "memory");
}

// =====================================================================
// LSTM kernel smem layout (floats)
// =====================================================================
#define LS_XV     0        // [280][8]: rows 0..7 x_t, 8..23 emb, 24..151 h0, 152..279 h1
#define LS_GATES  2240     // [8][512] partials from kgroup1 (interleaved cols)
#define LS_STAGE  6336     // 2 x (KC*512) = 32768
#define LS_B0     39104    // 512
#define LS_B1     39616    // 512
#define LS_EMBR   40128    // [8][16]
#define LS_MB     40256    // 2 mbarriers
#define LS_TOTAL  40260
#define LSTM_SMEM_BYTES (LS_TOTAL * 4)

// ---------------- LSTM GEMM: K-split (kg = 0/1 handles half of each chunk) ----------------
// No trailing sync; caller syncs before reading gates partials.
__device__ __forceinline__ void lstm_gemm(const float* __restrict__ gW, int K,
                                          const float* __restrict__ xv,
                                          float* stg, unsigned stg_u32,
                                          unsigned mb0, unsigned mb1, int &ph0, int &ph1,
                                          int g0, int r0g, int kg, int tid,
                                          ull acc[4][2]) {
    const int NC = (K + KC - 1) / KC;
    if (tid == 0) {
        int kc0 = (K < KC) ? K : KC;
        bulk_stage(stg_u32, gW, (unsigned)(kc0 * 512 * 4), mb0);
    }

    #pragma unroll 1
    for (int c = 0; c < NC; c++) {
        unsigned mcur = (c & 1) ? mb1 : mb0;
        int pcur = (c & 1) ? ph1 : ph0;
        mbar_wait(mcur, pcur);
        if (c & 1) ph1 ^= 1; else ph0 ^= 1;
        __syncthreads();   // chunk c data visible AND all threads done with c-1's buffer

        if (c + 1 < NC && tid == 0) {
            int kn = K - (c + 1) * KC; if (kn > KC) kn = KC;
            unsigned mnx = ((c + 1) & 1) ? mb1 : mb0;
            bulk_stage(stg_u32 + ((c + 1) & 1) * KCBYTES,
                       gW + (c + 1) * KC * 512, (unsigned)(kn * 512 * 4), mnx);
        }

        const float* buf = stg + (c & 1) * (KC * 512);
        const int kbase = c * KC;
        int kc = K - kbase; if (kc > KC) kc = KC;
        const int ks = kg ? 16 : 0;
        const int ke = kg ? kc : 16;   // kc >= 16 always (chunks are 24 or 32)

        #pragma unroll 8
        for (int kk = ks; kk < ke; kk++) {
            const ulonglong2 w = *reinterpret_cast<const ulonglong2*>(buf + (kk << 9) + g0);
            const float4 x = *reinterpret_cast<const float4*>(xv + ((kbase + kk) << 3) + r0g);
            ull d0 = dup2(x.x), d1 = dup2(x.y), d2 = dup2(x.z), d3 = dup2(x.w);
            ffma2(acc[0][0], w.x, d0); ffma2(acc[0][1], w.y, d0);
            ffma2(acc[1][0], w.x, d1); ffma2(acc[1][1], w.y, d1);
            ffma2(acc[2][0], w.x, d2); ffma2(acc[2][1], w.y, d2);
            ffma2(acc[3][0], w.x, d3); ffma2(acc[3][1], w.y, d3);
        }
    }
}

// =====================================================================
// Kernel 1: LSTM encoder — NT=512, K-split, in-register combine
// =====================================================================
__global__ __launch_bounds__(NT_L, 1)
void lstm_kernel(const float* __restrict__ x_hist, const int* __restrict__ turb_idx,
                 const float* __restrict__ turb_emb) {
    extern __shared__ float sm[];
    float* xv    = sm + LS_XV;
    float* gates = sm + LS_GATES;
    float* stg   = sm + LS_STAGE;
    float* b0s   = sm + LS_B0;
    float* b1s   = sm + LS_B1;
    float* embr  = sm + LS_EMBR;

    const int tid  = threadIdx.x;
    const int brow = blockIdx.x * RPB;

    const unsigned stg_u32 = smem_u32(stg);
    const unsigned mb0 = smem_u32(sm + LS_MB);
    const unsigned mb1 = mb0 + 8;

    // ---- init ----
    for (int i = tid; i < 2048; i += NT_L) xv[192 + i] = 0.0f;   // h0, h1 = 0
    for (int i = tid; i < 512; i += NT_L) { b0s[i] = g_b0[i]; b1s[i] = g_b1[i]; }
    if (tid < 128) {
        int r = tid >> 4, k = tid & 15;
        embr[r * 16 + k] = turb_emb[turb_idx[brow + r] * 16 + k];
    }
    if (tid == 0) {
        asm volatile("mbarrier.init.shared.b64 [%0], 1;" :: "r"(mb0) : "memory");
        asm volatile("mbarrier.init.shared.b64 [%0], 1;" :: "r"(mb1) : "memory");
    }
    __syncthreads();
    if (tid < 128) {
        int k = tid >> 3, r = tid & 7;
        xv[(8 + k) * 8 + r] = embr[r * 16 + k];   // constant emb part of in0
    }
    __syncthreads();

    const int lt  = tid & 255;        // lane within kgroup
    const int kg  = tid >> 8;         // 0/1 k-half
    const int u   = lt >> 1;          // unit 0..127
    const int g0  = u << 2;           // interleaved column base (i,f,g,o of unit u)
    const int r0g = (lt & 1) << 2;    // rows r0g..r0g+3

    float c0r[4] = {0.f, 0.f, 0.f, 0.f};
    float c1r[4] = {0.f, 0.f, 0.f, 0.f};
    int ph0 = 0, ph1 = 0;

    // x prefetch duty: kgroup1's first 64 threads (tid 256..319)
    const int xk = lt & 7, xr = (lt >> 3) & 7;
    float xnext = 0.f;
    if (tid >= 256 && tid < 320)
        xnext = __ldg(&x_hist[((brow + xr) * 96 + 0) * 8 + xk]);

    const float4 b0v = *reinterpret_cast<const float4*>(b0s + g0);
    const float4 b1v = *reinterpret_cast<const float4*>(b1s + g0);

    for (int t = 0; t < 96; t++) {
        if (tid >= 256 && tid < 320) {
            xv[xk * 8 + xr] = xnext;   // ordered by chunk-0 sync inside lstm_gemm
            if (t + 1 < 96) xnext = __ldg(&x_hist[((brow + xr) * 96 + (t + 1)) * 8 + xk]);
        }

        // ---- layer 0 ----
        ull acc[4][2];
        acc[0][0]=acc[0][1]=acc[1][0]=acc[1][1]=acc[2][0]=acc[2][1]=acc[3][0]=acc[3][1]=0ULL;
        lstm_gemm(g_W0cat, 152, xv, stg, stg_u32, mb0, mb1, ph0, ph1, g0, r0g, kg, tid, acc);
        if (kg == 1) {   // store partials
            #pragma unroll
            for (int ri = 0; ri < 4; ri++)
                *reinterpret_cast<ulonglong2*>(&gates[(r0g + ri) * 512 + g0]) =
                    make_ulonglong2(acc[ri][0], acc[ri][1]);
        }
        __syncthreads();
        if (kg == 0) {   // reduce + combine in registers
            float h[4];
            #pragma unroll
            for (int ri = 0; ri < 4; ri++) {
                const ulonglong2 p = *reinterpret_cast<const ulonglong2*>(&gates[(r0g + ri) * 512 + g0]);
                fadd2(acc[ri][0], p.x);
                fadd2(acc[ri][1], p.y);
                float2 pif = unpack2(acc[ri][0]);   // (i, f)
                float2 pgo = unpack2(acc[ri][1]);   // (g, o)
                float gi = pif.x + b0v.x, gf = pif.y + b0v.y;
                float gg = pgo.x + b0v.z, go = pgo.y + b0v.w;
                float cc = sigf(gf) * c0r[ri] + sigf(gi) * tanhf_fast(gg);
                c0r[ri] = cc;
                h[ri] = sigf(go) * tanhf_fast(cc);
            }
            *reinterpret_cast<float4*>(&xv[(24 + u) * 8 + r0g]) = make_float4(h[0], h[1], h[2], h[3]);
        }
        // h0 writes ordered by layer-1 chunk-0 sync

        // ---- layer 1 ----
        acc[0][0]=acc[0][1]=acc[1][0]=acc[1][1]=acc[2][0]=acc[2][1]=acc[3][0]=acc[3][1]=0ULL;
        lstm_gemm(g_W1cat, 256, xv + 24 * 8, stg, stg_u32, mb0, mb1, ph0, ph1, g0, r0g, kg, tid, acc);
        if (kg == 1) {
            #pragma unroll
            for (int ri = 0; ri < 4; ri++)
                *reinterpret_cast<ulonglong2*>(&gates[(r0g + ri) * 512 + g0]) =
                    make_ulonglong2(acc[ri][0], acc[ri][1]);
        }
        __syncthreads();
        if (kg == 0) {
            float h[4];
            #pragma unroll
            for (int ri = 0; ri < 4; ri++) {
                const ulonglong2 p = *reinterpret_cast<const ulonglong2*>(&gates[(r0g + ri) * 512 + g0]);
                fadd2(acc[ri][0], p.x);
                fadd2(acc[ri][1], p.y);
                float2 pif = unpack2(acc[ri][0]);
                float2 pgo = unpack2(acc[ri][1]);
                float gi = pif.x + b1v.x, gf = pif.y + b1v.y;
                float gg = pgo.x + b1v.z, go = pgo.y + b1v.w;
                float cc = sigf(gf) * c1r[ri] + sigf(gi) * tanhf_fast(gg);
                c1r[ri] = cc;
                h[ri] = sigf(go) * tanhf_fast(cc);
            }
            *reinterpret_cast<float4*>(&xv[(152 + u) * 8 + r0g]) = make_float4(h[0], h[1], h[2], h[3]);
        }
        // h1 writes ordered by next step's layer-0 chunk-0 sync
    }
    __syncthreads();

    // write enc_out (xv rows 152..279 = 1024 floats) to global, float4-coalesced
    {
        float4* src = reinterpret_cast<float4*>(xv + 152 * 8);
        float4* dst = reinterpret_cast<float4*>(g_enc + blockIdx.x * 1024);
        if (tid < 256) dst[tid] = src[tid];
    }
}

// =====================================================================
// Diffusion kernel (R9-proven, unchanged)
// =====================================================================
#define DS_ENC    0        // [128 u][8 r]
#define DS_MH1    1024
#define DS_A1     2048     // 12800
#define DS_W1Y    14848
#define DS_W3     14976
#define DS_BM2    15104
#define DS_EMBT   15232
#define DS_XFT    15360
#define DS_HES    15408
#define DS_CY     15440
#define DS_CE     15540
#define DS_RED    15640
#define DS_TOTAL  15672
#define DIFF_SMEM_BYTES (DS_TOTAL * 4)

__device__ __forceinline__ void barh(int half) {
    asm volatile("bar.sync %0, 128;" :: "r"(half + 1) : "memory");
}

__global__ __launch_bounds__(NT_D, 1)
void diffusion_kernel(const float* __restrict__ x_future, const float* __restrict__ y0,
                      const int* __restrict__ turb_idx, const float* __restrict__ init_noise,
                      const float* __restrict__ turb_emb,
                      const float* __restrict__ b1m, const float* __restrict__ b2m,
                      const float* __restrict__ W3, const float* __restrict__ b3p,
                      float* __restrict__ out) {
    extern __shared__ float sm[];
    float* encs  = sm + DS_ENC;
    float* mh1   = sm + DS_MH1;
    float* a1s   = sm + DS_A1;
    float* w1ys  = sm + DS_W1Y;
    float* w3s   = sm + DS_W3;
    float* bm2s  = sm + DS_BM2;
    float* embT  = sm + DS_EMBT;
    float* xfT   = sm + DS_XFT;
    float* hes   = sm + DS_HES;
    float* cys   = sm + DS_CY;
    float* ces   = sm + DS_CE;
    float* red   = sm + DS_RED;

    const int tid  = threadIdx.x;
    const int brow = blockIdx.x * RPB;

    for (int i = tid; i < 12800; i += NT_D) a1s[i] = g_A1t[i];
    {
        float4* src = reinterpret_cast<float4*>(g_enc + blockIdx.x * 1024);
        float4* dst = reinterpret_cast<float4*>(encs);
        if (tid < 256) dst[tid] = src[tid];
    }
    if (tid < 128) {
        int k = tid >> 3, r = tid & 7;
        embT[k * 8 + r] = turb_emb[turb_idx[brow + r] * 16 + k];
        w1ys[tid] = g_W1T[151 * 128 + tid];
        w3s[tid]  = W3[tid];
        bm2s[tid] = b2m[tid];
    }
    if (tid < 100) { cys[tid] = g_cy[tid]; ces[tid] = g_ce[tid]; }
    __syncthreads();

    const int uu   = tid & 127;
    const int half = tid >> 7;
    const int local = tid & 127;
    const int r0d = half * 4;
    const float b3v = __ldg(&b3p[0]);

    float w2r[128];
    #pragma unroll
    for (int u = 0; u < 128; u++) w2r[u] = __ldg(&g_W2s[(u << 7) + uu]);

    const float w1yv = w1ys[uu];
    const float w3v  = w3s[uu];
    const float bm2v = bm2s[uu];
    const ull bm2p = pack2(bm2v, bm2v);

    float ypa[4];
    #pragma unroll
    for (int j = 0; j < 4; j++) ypa[j] = __ldg(&y0[brow + r0d + j]);

    const int wih = (tid >> 5) & 3;
    const int lane = tid & 31;

    for (int p = 0; p < 8; p++) {
        if (local < 24) {
            int k = local >> 2, rl = local & 3;
            xfT[half * 24 + k * 4 + rl] = __ldg(&x_future[(brow + r0d + rl) * 48 + p * 6 + k]);
        }
        if (local < 16) {
            int j = local & 7;
            float f = __expf(-logf(10000.0f) * (float)j / 8.0f);
            float a = (float)p * f;
            hes[half * 16 + local] = (local < 8) ? cosf(a) : sinf(a);
        }
        float yra[4];
        #pragma unroll
        for (int j = 0; j < 4; j++) yra[j] = __ldg(&init_noise[p * 1024 + brow + r0d + j]);
        barh(half);

        float4 base = make_float4(0.f, 0.f, 0.f, 0.f);
        {
            #pragma unroll 8
            for (int k = 0; k < 128; k++) {
                float w = __ldg(&g_W1T[(k << 7) + uu]);
                const float4 h = *reinterpret_cast<const float4*>(&encs[k * 8 + r0d]);
                base.x += w * h.x; base.y += w * h.y; base.z += w * h.z; base.w += w * h.w;
            }
            #pragma unroll
            for (int k = 0; k < 6; k++) {
                float w = __ldg(&g_W1T[((128 + k) << 7) + uu]);
                const float4 x = *reinterpret_cast<const float4*>(&xfT[half * 24 + k * 4]);
                base.x += w * x.x; base.y += w * x.y; base.z += w * x.z; base.w += w * x.w;
            }
            #pragma unroll
            for (int k = 0; k < 16; k++) {
                float w = __ldg(&g_W1T[((134 + k) << 7) + uu]);
                const float* ep = &embT[k * 8 + r0d];
                base.x += w * ep[0]; base.y += w * ep[1]; base.z += w * ep[2]; base.w += w * ep[3];
            }
            {
                float w = __ldg(&g_W1T[(150 << 7) + uu]);
                base.x += w * ypa[0]; base.y += w * ypa[1]; base.z += w * ypa[2]; base.w += w * ypa[3];
            }
            float hsum = 0.f;
            #pragma unroll
            for (int k = 0; k < 16; k++) hsum += __ldg(&g_W1T[((168 + k) << 7) + uu]) * hes[half * 16 + k];
            float bb = __ldg(&b1m[uu]) + hsum;
            base.x += bb; base.y += bb; base.z += bb; base.w += bb;
        }

        for (int tt = 99; tt >= 0; tt--) {
            {
                float av = a1s[tt * 128 + uu];
                float4 m;
                m.x = fmaxf(base.x + yra[0] * w1yv + av, 0.f);
                m.y = fmaxf(base.y + yra[1] * w1yv + av, 0.f);
                m.z = fmaxf(base.z + yra[2] * w1yv + av, 0.f);
                m.w = fmaxf(base.w + yra[3] * w1yv + av, 0.f);
                *reinterpret_cast<float4*>(&mh1[(uu << 3) + r0d]) = m;
            }
            barh(half);

            {
                ull acc01 = bm2p;
                ull acc23 = bm2p;
                #pragma unroll
                for (int u = 0; u < 128; u++) {
                    const ulonglong2 h = *reinterpret_cast<const ulonglong2*>(&mh1[(u << 3) + r0d]);
                    ull dw = dup2(w2r[u]);
                    ffma2(acc01, dw, h.x);
                    ffma2(acc23, dw, h.y);
                }
                float2 a01 = unpack2(acc01);
                float2 a23 = unpack2(acc23);
                float e0 = fmaxf(a01.x, 0.f) * w3v;
                float e1 = fmaxf(a01.y, 0.f) * w3v;
                float e2 = fmaxf(a23.x, 0.f) * w3v;
                float e3 = fmaxf(a23.y, 0.f) * w3v;
                #pragma unroll
                for (int off = 16; off > 0; off >>= 1) {
                    e0 += __shfl_down_sync(0xffffffffu, e0, off);
                    e1 += __shfl_down_sync(0xffffffffu, e1, off);
                    e2 += __shfl_down_sync(0xffffffffu, e2, off);
                    e3 += __shfl_down_sync(0xffffffffu, e3, off);
                }
                if (lane == 0)
                    *reinterpret_cast<float4*>(&red[half * 16 + wih * 4]) = make_float4(e0, e1, e2, e3);
            }
            barh(half);

            {
                const float4 q0 = *reinterpret_cast<const float4*>(&red[half * 16 + 0]);
                const float4 q1 = *reinterpret_cast<const float4*>(&red[half * 16 + 4]);
                const float4 q2 = *reinterpret_cast<const float4*>(&red[half * 16 + 8]);
                const float4 q3 = *reinterpret_cast<const float4*>(&red[half * 16 + 12]);
                float cy = cys[tt], ce = ces[tt];
                yra[0] = cy * yra[0] - ce * (b3v + q0.x + q1.x + q2.x + q3.x);
                yra[1] = cy * yra[1] - ce * (b3v + q0.y + q1.y + q2.y + q3.y);
                yra[2] = cy * yra[2] - ce * (b3v + q0.z + q1.z + q2.z + q3.z);
                yra[3] = cy * yra[3] - ce * (b3v + q0.w + q1.w + q2.w + q3.w);
            }
        }

        if (local < 4) {
            float v = (local == 0) ? yra[0] : (local == 1) ? yra[1] : (local == 2) ? yra[2] : yra[3];
            out[(brow + r0d + local) * 8 + p] = v;
        }
        #pragma unroll
        for (int j = 0; j < 4; j++) ypa[j] = yra[j];
    }
}

// ---------------- launch ----------------
extern "C" void kernel_launch(void* const* d_in, const int* in_sizes, int n_in,
                              void* d_out, int out_size) {
    const float* x_hist     = (const float*)d_in[0];
    const float* x_future   = (const float*)d_in[1];
    const float* y0         = (const float*)d_in[2];
    const int*   turb_idx   = (const int*)d_in[3];
    const float* init_noise = (const float*)d_in[5];
    const float* turb_emb   = (const float*)d_in[6];
    const float* W_ih0      = (const float*)d_in[7];
    const float* W_hh0      = (const float*)d_in[8];
    const float* b_ih0      = (const float*)d_in[9];
    const float* b_hh0      = (const float*)d_in[10];
    const float* W_ih1      = (const float*)d_in[11];
    const float* W_hh1      = (const float*)d_in[12];
    const float* b_ih1      = (const float*)d_in[13];
    const float* b_hh1      = (const float*)d_in[14];
    const float* W1         = (const float*)d_in[15];
    const float* b1m        = (const float*)d_in[16];
    const float* W2         = (const float*)d_in[17];
    const float* b2m        = (const float*)d_in[18];
    const float* W3         = (const float*)d_in[19];
    const float* b3         = (const float*)d_in[20];
    float* out = (float*)d_out;

    prologue_kernel<<<128, 256>>>(W_ih0, W_hh0, b_ih0, b_hh0,
                                  W_ih1, W_hh1, b_ih1, b_hh1, W1, W2);

    cudaFuncSetAttribute(lstm_kernel, cudaFuncAttributeMaxDynamicSharedMemorySize, LSTM_SMEM_BYTES);
    lstm_kernel<<<NBLK, NT_L, LSTM_SMEM_BYTES>>>(x_hist, turb_idx, turb_emb);

    cudaFuncSetAttribute(diffusion_kernel, cudaFuncAttributeMaxDynamicSharedMemorySize, DIFF_SMEM_BYTES);
    diffusion_kernel<<<NBLK, NT_D, DIFF_SMEM_BYTES>>>(x_future, y0, turb_idx, init_noise,
                                                      turb_emb, b1m, b2m, W3, b3, out);
}

// round 14
// speedup vs baseline: 1.0854x; 1.0854x over previous
#include <cuda_runtime.h>
#include <math.h>

#define NT 256
#define RPB 8
#define NBLK 128
#define KC 32
#define KCBYTES (KC * 512 * 4)

typedef unsigned long long ull;

// ---------------- device scratch ----------------
// Interleaved gate layout: column c = 4*u + gate, gate in {i,f,g,o}
__device__ float g_W0ext[160 * 512];   // [k][c]: k 0..7 x, 8..23 emb, 24..31 ZERO, 32..159 W_hh0
__device__ float g_W1cat[256 * 512];   // [k][c]: k 0..127 W_ih1, 128..255 W_hh1
__device__ float g_b0[512];            // interleaved
__device__ float g_b1[512];            // interleaved
__device__ float g_W1T[184 * 128];     // [k][u]  (diffusion)
__device__ float g_W2s[128 * 128];     // [u][v] = W2[v][u]
__device__ float g_A1t[100 * 128];
__device__ float g_cy[100];
__device__ float g_ce[100];

// ---------------- prologue ----------------
__global__ void prologue_kernel(const float* __restrict__ W_ih0, const float* __restrict__ W_hh0,
                                const float* __restrict__ b_ih0, const float* __restrict__ b_hh0,
                                const float* __restrict__ W_ih1, const float* __restrict__ W_hh1,
                                const float* __restrict__ b_ih1, const float* __restrict__ b_hh1,
                                const float* __restrict__ W1,    const float* __restrict__ W2) {
    int tid = blockIdx.x * blockDim.x + threadIdx.x;
    int nth = gridDim.x * blockDim.x;

    for (int i = tid; i < 160 * 512; i += nth) {
        int k = i >> 9, c = i & 511;
        int u = c >> 2, gi = c & 3;
        int row = gi * 128 + u;
        float v;
        if (k < 24)      v = W_ih0[row * 24 + k];
        else if (k < 32) v = 0.0f;
        else             v = W_hh0[row * 128 + (k - 32)];
        g_W0ext[i] = v;
    }
    for (int i = tid; i < 256 * 512; i += nth) {
        int k = i >> 9, c = i & 511;
        int u = c >> 2, gi = c & 3;
        int row = gi * 128 + u;
        g_W1cat[i] = (k < 128) ? W_ih1[row * 128 + k] : W_hh1[row * 128 + (k - 128)];
    }
    for (int i = tid; i < 512; i += nth) {
        int u = i >> 2, gi = i & 3;
        int row = gi * 128 + u;
        g_b0[i] = b_ih0[row] + b_hh0[row];
        g_b1[i] = b_ih1[row] + b_hh1[row];
    }
    for (int i = tid; i < 184 * 128; i += nth) {
        int k = i >> 7, u = i & 127;
        g_W1T[i] = W1[u * 184 + k];
    }
    for (int i = tid; i < 128 * 128; i += nth) {
        int u = i >> 7, v = i & 127;
        g_W2s[i] = W2[v * 128 + u];
    }
    for (int i = tid; i < 100 * 128; i += nth) {
        int t = i >> 7, u = i & 127;
        float acc = 0.f;
        #pragma unroll
        for (int j = 0; j < 8; j++) {
            float f = expf(-logf(10000.0f) * (float)j / 8.0f);
            float a = (float)t * f;
            acc += W1[u * 184 + 152 + j] * cosf(a);
            acc += W1[u * 184 + 160 + j] * sinf(a);
        }
        g_A1t[i] = acc;
    }
    if (tid == 0) {
        float ab = 1.0f;
        for (int t = 0; t < 100; t++) {
            float beta  = 1e-4f + (0.02f - 1e-4f) * (float)t / 99.0f;
            float alpha = 1.0f - beta;
            ab *= alpha;
            if (t == 0) {
                float p = sqrtf(ab) + 1e-8f;
                g_cy[0] = 1.0f / p;
                g_ce[0] = sqrtf(1.0f - ab) / p;
            } else {
                float inv = 1.0f / (sqrtf(alpha) + 1e-8f);
                g_cy[t] = inv;
                g_ce[t] = beta / (sqrtf(1.0f - ab) + 1e-8f) * inv;
            }
        }
    }
}

// ---------------- fast math helpers ----------------
__device__ __forceinline__ float sigf(float x) {
    float xc = fminf(fmaxf(x, -30.f), 30.f);
    return __fdividef(1.0f, 1.0f + __expf(-xc));
}
__device__ __forceinline__ float tanhf_fast(float x) {
    float xc = fminf(fmaxf(x, -15.f), 15.f);
    float e = __expf(2.0f * xc);
    return __fdividef(e - 1.0f, e + 1.0f);
}
__device__ __forceinline__ void ffma2(ull &d, ull a, ull b) {
    asm("fma.rn.f32x2 %0, %1, %2, %0;" : "+l"(d) : "l"(a), "l"(b));
}
__device__ __forceinline__ ull dup2(float x) {
    ull r;
    asm("mov.b64 %0, {%1, %1};" : "=l"(r) : "f"(x));
    return r;
}
__device__ __forceinline__ ull pack2(float lo, float hi) {
    ull r;
    asm("mov.b64 %0, {%1, %2};" : "=l"(r) : "f"(lo), "f"(hi));
    return r;
}
__device__ __forceinline__ float2 unpack2(ull v) {
    float2 r;
    asm("mov.b64 {%0, %1}, %2;" : "=f"(r.x), "=f"(r.y) : "l"(v));
    return r;
}
__device__ __forceinline__ unsigned smem_u32(const void* p) {
    unsigned a;
    asm("{ .reg .u64 t; cvta.to.shared.u64 t, %1; cvt.u32.u64 %0, t; }" : "=r"(a) : "l"(p));
    return a;
}

// ---------------- bulk staging (TMA path) ----------------
__device__ __forceinline__ void bulk_stage(unsigned dst, const float* __restrict__ src,
                                           unsigned bytes, unsigned mbar) {
    asm volatile("mbarrier.arrive.expect_tx.shared.b64 _, [%0], %1;"
                 :: "r"(mbar), "r"(bytes) : "memory");
    asm volatile("cp.async.bulk.shared::cluster.global.mbarrier::complete_tx::bytes [%0], [%1], %2, [%3];"
                 :: "r"(dst), "l"(src), "r"(bytes), "r"(mbar) : "memory");
}
__device__ __forceinline__ void mbar_wait(unsigned mbar, int phase) {
    asm volatile(
        "{\n\t.reg .pred P1;\n\t"
        "WAIT_LOOP_%=:\n\t"
        "mbarrier.try_wait.parity.shared.b64 P1, [%0], %1;\n\t"
        "@P1 bra.uni WAIT_DONE_%=;\n\t"
        "bra.uni WAIT_LOOP_%=;\n\t"
        "WAIT_DONE_%=:\n\t}"
        :: "r"(mbar), "r"(phase) : "memory");
}

// ---------------- smem layout (floats) ----------------
#define SM_XFIX   0        // [32][8]: rows 0..7 x_t, 8..23 emb, 24..31 zero
#define SM_H0A    256      // [128][8]
#define SM_H0B    1280
#define SM_H1A    2304
#define SM_H1B    3328
#define SM_STAGE  4352     // 2 x (KC*512) = 32768 (byte off 17408, 16B aligned)
#define SM_B0     37120    // 512 interleaved
#define SM_B1     37632    // 512
#define SM_EMBR   38144    // [8][16]
#define SM_EMBT   38272    // [16][8]
#define SM_MH1    38400    // [128][8]
#define SM_W1Y    39424
#define SM_W3     39552
#define SM_BM2    39680
#define SM_XFT    39808    // 48
#define SM_HES    39856    // 32
#define SM_CY     39888
#define SM_CE     39988
#define SM_RED    40088    // 32
#define SM_A1     40120    // 12800
#define SM_MB     52920    // 2 mbarriers (byte off 211680, 8B aligned)
#define SM_TOTAL  52924
#define SMEM_BYTES (SM_TOTAL * 4)

__device__ __forceinline__ void barh(int half) {
    asm volatile("bar.sync %0, 128;" :: "r"(half + 1) : "memory");
}

// ---------------- main fused kernel ----------------
__global__ __launch_bounds__(NT, 1)
void fused_kernel(const float* __restrict__ x_hist, const float* __restrict__ x_future,
                  const float* __restrict__ y0, const int* __restrict__ turb_idx,
                  const float* __restrict__ init_noise, const float* __restrict__ turb_emb,
                  const float* __restrict__ b1m, const float* __restrict__ b2m,
                  const float* __restrict__ W3, const float* __restrict__ b3p,
                  float* __restrict__ out) {
    extern __shared__ float sm[];
    float* xfix  = sm + SM_XFIX;
    float* h0A   = sm + SM_H0A;
    float* h0B   = sm + SM_H0B;
    float* h1A   = sm + SM_H1A;
    float* h1B   = sm + SM_H1B;
    float* stg   = sm + SM_STAGE;
    float* b0s   = sm + SM_B0;
    float* b1s   = sm + SM_B1;
    float* embr  = sm + SM_EMBR;
    float* embT  = sm + SM_EMBT;
    float* mh1   = sm + SM_MH1;
    float* w1ys  = sm + SM_W1Y;
    float* w3s   = sm + SM_W3;
    float* bm2s  = sm + SM_BM2;
    float* xfT   = sm + SM_XFT;
    float* hes   = sm + SM_HES;
    float* cys   = sm + SM_CY;
    float* ces   = sm + SM_CE;
    float* red   = sm + SM_RED;
    float* a1s   = sm + SM_A1;

    const int tid  = threadIdx.x;
    const int brow = blockIdx.x * RPB;

    const unsigned stg_u32 = smem_u32(stg);
    const unsigned mb0 = smem_u32(sm + SM_MB);
    const unsigned mb1 = mb0 + 8;

    // ---- init ----
    for (int i = tid; i < 256; i += NT) xfix[i] = 0.0f;
    for (int i = tid; i < 4096; i += NT) h0A[i] = 0.0f;   // h0A,h0B,h1A,h1B
    for (int i = tid; i < 512; i += NT) { b0s[i] = g_b0[i]; b1s[i] = g_b1[i]; }
    for (int i = tid; i < 12800; i += NT) a1s[i] = g_A1t[i];
    if (tid < 128) {
        int r = tid >> 4, k = tid & 15;
        embr[r * 16 + k] = turb_emb[turb_idx[brow + r] * 16 + k];
    }
    if (tid < 128) {
        w1ys[tid] = g_W1T[151 * 128 + tid];
        w3s[tid]  = W3[tid];
        bm2s[tid] = b2m[tid];
    }
    if (tid < 100) { cys[tid] = g_cy[tid]; ces[tid] = g_ce[tid]; }
    if (tid == 0) {
        asm volatile("mbarrier.init.shared.b64 [%0], 1;" :: "r"(mb0) : "memory");
        asm volatile("mbarrier.init.shared.b64 [%0], 1;" :: "r"(mb1) : "memory");
    }
    __syncthreads();
    if (tid < 128) {
        int k = tid >> 3, r = tid & 7;
        float v = embr[r * 16 + k];
        embT[k * 8 + r] = v;
        xfix[(8 + k) * 8 + r] = v;   // constant emb rows
    }
    // x_0 into xfix rows 0..7
    const int xk = tid & 7, xr = tid >> 3;
    if (tid < 64) xfix[xk * 8 + xr] = __ldg(&x_hist[((brow + xr) * 96 + 0) * 8 + xk]);
    __syncthreads();

    const int u   = tid >> 1;        // unit 0..127
    const int g0  = u << 2;          // interleaved cols (i,f,g,o) of unit u
    const int r0g = (tid & 1) << 2;  // rows r0g..r0g+3

    const float4 b0v = *reinterpret_cast<const float4*>(b0s + g0);
    const float4 b1v = *reinterpret_cast<const float4*>(b1s + g0);

    float c0r[4] = {0.f, 0.f, 0.f, 0.f};
    float c1r[4] = {0.f, 0.f, 0.f, 0.f};

    float* h0cur = h0A; float* h0nxt = h0B;
    float* h1cur = h1A; float* h1nxt = h1B;
    int par = 0, phase0 = 0, phase1 = 0;

    float xnext = 0.f;
    if (tid < 64) xnext = __ldg(&x_hist[((brow + xr) * 96 + 1) * 8 + xk]);

    if (tid == 0) bulk_stage(stg_u32, g_W0ext, KCBYTES, mb0);

    // =================== LSTM encoder: 96 steps x 13 chunks ===================
    for (int t = 0; t < 96; t++) {
        ull a00 = 0, a01 = 0, a10 = 0, a11 = 0, a20 = 0, a21 = 0, a30 = 0, a31 = 0;

        #pragma unroll 1
        for (int cc = 0; cc < 13; cc++) {
            // wait chunk cc
            if (par == 0) { mbar_wait(mb0, phase0); phase0 ^= 1; }
            else          { mbar_wait(mb1, phase1); phase1 ^= 1; }
            __syncthreads();   // chunk cc visible AND all threads done with buffer par^1

            // issue chunk cc+1 (wraps to next step's chunk 0)
            if (tid == 0 && !(t == 95 && cc == 12)) {
                int nc = (cc + 1 == 13) ? 0 : cc + 1;
                const float* src = (nc < 5) ? (g_W0ext + nc * KC * 512)
                                            : (g_W1cat + (nc - 5) * KC * 512);
                bulk_stage(stg_u32 + (unsigned)(par ^ 1) * KCBYTES, src, KCBYTES,
                           (par == 0) ? mb1 : mb0);
            }

            const float* buf = stg + par * (KC * 512);
            const float* xb;
            if (cc == 0)      xb = xfix;
            else if (cc < 5)  xb = h0cur + (cc - 1) * 256;
            else if (cc < 9)  xb = h0nxt + (cc - 5) * 256;
            else              xb = h1cur + (cc - 9) * 256;

            #pragma unroll 8
            for (int kk = 0; kk < KC; kk++) {
                const ulonglong2 w = *reinterpret_cast<const ulonglong2*>(buf + (kk << 9) + g0);
                const float4 x = *reinterpret_cast<const float4*>(xb + (kk << 3) + r0g);
                ull d0 = dup2(x.x), d1 = dup2(x.y), d2 = dup2(x.z), d3 = dup2(x.w);
                ffma2(a00, w.x, d0); ffma2(a01, w.y, d0);
                ffma2(a10, w.x, d1); ffma2(a11, w.y, d1);
                ffma2(a20, w.x, d2); ffma2(a21, w.y, d2);
                ffma2(a30, w.x, d3); ffma2(a31, w.y, d3);
            }
            par ^= 1;

            if (cc == 4) {
                // combine layer 0 in registers -> h0nxt
                float h[4];
                {
                    float2 pif, pgo;
                    pif = unpack2(a00); pgo = unpack2(a01);
                    {
                        float gi = pif.x + b0v.x, gf = pif.y + b0v.y;
                        float gg = pgo.x + b0v.z, go = pgo.y + b0v.w;
                        float cv = sigf(gf) * c0r[0] + sigf(gi) * tanhf_fast(gg);
                        c0r[0] = cv; h[0] = sigf(go) * tanhf_fast(cv);
                    }
                    pif = unpack2(a10); pgo = unpack2(a11);
                    {
                        float gi = pif.x + b0v.x, gf = pif.y + b0v.y;
                        float gg = pgo.x + b0v.z, go = pgo.y + b0v.w;
                        float cv = sigf(gf) * c0r[1] + sigf(gi) * tanhf_fast(gg);
                        c0r[1] = cv; h[1] = sigf(go) * tanhf_fast(cv);
                    }
                    pif = unpack2(a20); pgo = unpack2(a21);
                    {
                        float gi = pif.x + b0v.x, gf = pif.y + b0v.y;
                        float gg = pgo.x + b0v.z, go = pgo.y + b0v.w;
                        float cv = sigf(gf) * c0r[2] + sigf(gi) * tanhf_fast(gg);
                        c0r[2] = cv; h[2] = sigf(go) * tanhf_fast(cv);
                    }
                    pif = unpack2(a30); pgo = unpack2(a31);
                    {
                        float gi = pif.x + b0v.x, gf = pif.y + b0v.y;
                        float gg = pgo.x + b0v.z, go = pgo.y + b0v.w;
                        float cv = sigf(gf) * c0r[3] + sigf(gi) * tanhf_fast(gg);
                        c0r[3] = cv; h[3] = sigf(go) * tanhf_fast(cv);
                    }
                }
                *reinterpret_cast<float4*>(&h0nxt[u * 8 + r0g]) = make_float4(h[0], h[1], h[2], h[3]);
                a00 = a01 = a10 = a11 = a20 = a21 = a30 = a31 = 0ULL;
                // x_{t+1} (readers of x_t finished at chunk-1 sync)
                if (tid < 64) {
                    xfix[xk * 8 + xr] = xnext;
                    if (t + 2 < 97 && t + 1 < 96 && t + 2 <= 96) {}
                    if (t + 2 < 97) {}
                    if (t + 2 <= 96 && t + 2 < 97) {}
                    if (t + 2 < 97 && (t + 2) <= 96) {}
                    if (t + 2 < 97) xnext = (t + 2 < 97 && t + 2 <= 96 && (t + 2) < 97 && (t + 2) <= 96)
                        ? ((t + 2 <= 95 + 1) ? ((t + 2 < 97) ? 0.f : 0.f) : 0.f) : 0.f;
                    // (simplified below)
                    if (t + 2 <= 96) {
                        int tn = t + 2;
                        if (tn < 96) xnext = __ldg(&x_hist[((brow + xr) * 96 + tn) * 8 + xk]);
                    }
                }
            } else if (cc == 12) {
                // combine layer 1 in registers -> h1nxt
                float h[4];
                {
                    float2 pif, pgo;
                    pif = unpack2(a00); pgo = unpack2(a01);
                    {
                        float gi = pif.x + b1v.x, gf = pif.y + b1v.y;
                        float gg = pgo.x + b1v.z, go = pgo.y + b1v.w;
                        float cv = sigf(gf) * c1r[0] + sigf(gi) * tanhf_fast(gg);
                        c1r[0] = cv; h[0] = sigf(go) * tanhf_fast(cv);
                    }
                    pif = unpack2(a10); pgo = unpack2(a11);
                    {
                        float gi = pif.x + b1v.x, gf = pif.y + b1v.y;
                        float gg = pgo.x + b1v.z, go = pgo.y + b1v.w;
                        float cv = sigf(gf) * c1r[1] + sigf(gi) * tanhf_fast(gg);
                        c1r[1] = cv; h[1] = sigf(go) * tanhf_fast(cv);
                    }
                    pif = unpack2(a20); pgo = unpack2(a21);
                    {
                        float gi = pif.x + b1v.x, gf = pif.y + b1v.y;
                        float gg = pgo.x + b1v.z, go = pgo.y + b1v.w;
                        float cv = sigf(gf) * c1r[2] + sigf(gi) * tanhf_fast(gg);
                        c1r[2] = cv; h[2] = sigf(go) * tanhf_fast(cv);
                    }
                    pif = unpack2(a30); pgo = unpack2(a31);
                    {
                        float gi = pif.x + b1v.x, gf = pif.y + b1v.y;
                        float gg = pgo.x + b1v.z, go = pgo.y + b1v.w;
                        float cv = sigf(gf) * c1r[3] + sigf(gi) * tanhf_fast(gg);
                        c1r[3] = cv; h[3] = sigf(go) * tanhf_fast(cv);
                    }
                }
                *reinterpret_cast<float4*>(&h1nxt[u * 8 + r0g]) = make_float4(h[0], h[1], h[2], h[3]);
            }
        }

        { float* tmp = h0cur; h0cur = h0nxt; h0nxt = tmp; }
        { float* tmp = h1cur; h1cur = h1nxt; h1nxt = tmp; }
    }
    __syncthreads();
    const float* encf = h1cur;   // final enc_out [128 u][8 r]

    // =================== AR + diffusion (R12-proven, two halves) ===================
    const int half = tid >> 7;
    const int local = tid & 127;
    const int uu = tid & 127;
    const int r0d = half * 4;
    const float b3v = __ldg(&b3p[0]);

    float w2r[128];
    #pragma unroll
    for (int uw = 0; uw < 128; uw++) w2r[uw] = __ldg(&g_W2s[(uw << 7) + uu]);

    const float w1yv = w1ys[uu];
    const float w3v  = w3s[uu];
    const float bm2v = bm2s[uu];
    const ull bm2p = pack2(bm2v, bm2v);

    float ypa[4];
    #pragma unroll
    for (int j = 0; j < 4; j++) ypa[j] = __ldg(&y0[brow + r0d + j]);

    const int wih = (tid >> 5) & 3;
    const int lane = tid & 31;

    for (int p = 0; p < 8; p++) {
        if (local < 24) {
            int k = local >> 2, rl = local & 3;
            xfT[half * 24 + k * 4 + rl] = __ldg(&x_future[(brow + r0d + rl) * 48 + p * 6 + k]);
        }
        if (local < 16) {
            int j = local & 7;
            float f = __expf(-logf(10000.0f) * (float)j / 8.0f);
            float a = (float)p * f;
            hes[half * 16 + local] = (local < 8) ? cosf(a) : sinf(a);
        }
        float yra[4];
        #pragma unroll
        for (int j = 0; j < 4; j++) yra[j] = __ldg(&init_noise[p * 1024 + brow + r0d + j]);
        barh(half);

        float4 base = make_float4(0.f, 0.f, 0.f, 0.f);
        {
            #pragma unroll 8
            for (int k = 0; k < 128; k++) {
                float w = __ldg(&g_W1T[(k << 7) + uu]);
                const float4 h = *reinterpret_cast<const float4*>(&encf[k * 8 + r0d]);
                base.x += w * h.x; base.y += w * h.y; base.z += w * h.z; base.w += w * h.w;
            }
            #pragma unroll
            for (int k = 0; k < 6; k++) {
                float w = __ldg(&g_W1T[((128 + k) << 7) + uu]);
                const float4 x = *reinterpret_cast<const float4*>(&xfT[half * 24 + k * 4]);
                base.x += w * x.x; base.y += w * x.y; base.z += w * x.z; base.w += w * x.w;
            }
            #pragma unroll
            for (int k = 0; k < 16; k++) {
                float w = __ldg(&g_W1T[((134 + k) << 7) + uu]);
                const float* ep = &embT[k * 8 + r0d];
                base.x += w * ep[0]; base.y += w * ep[1]; base.z += w * ep[2]; base.w += w * ep[3];
            }
            {
                float w = __ldg(&g_W1T[(150 << 7) + uu]);
                base.x += w * ypa[0]; base.y += w * ypa[1]; base.z += w * ypa[2]; base.w += w * ypa[3];
            }
            float hsum = 0.f;
            #pragma unroll
            for (int k = 0; k < 16; k++) hsum += __ldg(&g_W1T[((168 + k) << 7) + uu]) * hes[half * 16 + k];
            float bb = __ldg(&b1m[uu]) + hsum;
            base.x += bb; base.y += bb; base.z += bb; base.w += bb;
        }

        for (int tt = 99; tt >= 0; tt--) {
            {
                float av = a1s[tt * 128 + uu];
                float4 m;
                m.x = fmaxf(base.x + yra[0] * w1yv + av, 0.f);
                m.y = fmaxf(base.y + yra[1] * w1yv + av, 0.f);
                m.z = fmaxf(base.z + yra[2] * w1yv + av, 0.f);
                m.w = fmaxf(base.w + yra[3] * w1yv + av, 0.f);
                *reinterpret_cast<float4*>(&mh1[(uu << 3) + r0d]) = m;
            }
            barh(half);

            {
                ull acc01 = bm2p;
                ull acc23 = bm2p;
                #pragma unroll
                for (int uw = 0; uw < 128; uw++) {
                    const ulonglong2 h = *reinterpret_cast<const ulonglong2*>(&mh1[(uw << 3) + r0d]);
                    ull dw = dup2(w2r[uw]);
                    ffma2(acc01, dw, h.x);
                    ffma2(acc23, dw, h.y);
                }
                float2 a01 = unpack2(acc01);
                float2 a23 = unpack2(acc23);
                float e0 = fmaxf(a01.x, 0.f) * w3v;
                float e1 = fmaxf(a01.y, 0.f) * w3v;
                float e2 = fmaxf(a23.x, 0.f) * w3v;
                float e3 = fmaxf(a23.y, 0.f) * w3v;
                #pragma unroll
                for (int off = 16; off > 0; off >>= 1) {
                    e0 += __shfl_down_sync(0xffffffffu, e0, off);
                    e1 += __shfl_down_sync(0xffffffffu, e1, off);
                    e2 += __shfl_down_sync(0xffffffffu, e2, off);
                    e3 += __shfl_down_sync(0xffffffffu, e3, off);
                }
                if (lane == 0)
                    *reinterpret_cast<float4*>(&red[half * 16 + wih * 4]) = make_float4(e0, e1, e2, e3);
            }
            barh(half);

            {
                const float4 q0 = *reinterpret_cast<const float4*>(&red[half * 16 + 0]);
                const float4 q1 = *reinterpret_cast<const float4*>(&red[half * 16 + 4]);
                const float4 q2 = *reinterpret_cast<const float4*>(&red[half * 16 + 8]);
                const float4 q3 = *reinterpret_cast<const float4*>(&red[half * 16 + 12]);
                float cy = cys[tt], ce = ces[tt];
                yra[0] = cy * yra[0] - ce * (b3v + q0.x + q1.x + q2.x + q3.x);
                yra[1] = cy * yra[1] - ce * (b3v + q0.y + q1.y + q2.y + q3.y);
                yra[2] = cy * yra[2] - ce * (b3v + q0.z + q1.z + q2.z + q3.z);
                yra[3] = cy * yra[3] - ce * (b3v + q0.w + q1.w + q2.w + q3.w);
            }
        }

        if (local < 4) {
            float v = (local == 0) ? yra[0] : (local == 1) ? yra[1] : (local == 2) ? yra[2] : yra[3];
            out[(brow + r0d + local) * 8 + p] = v;
        }
        #pragma unroll
        for (int j = 0; j < 4; j++) ypa[j] = yra[j];
    }
}

// ---------------- launch ----------------
extern "C" void kernel_launch(void* const* d_in, const int* in_sizes, int n_in,
                              void* d_out, int out_size) {
    const float* x_hist     = (const float*)d_in[0];
    const float* x_future   = (const float*)d_in[1];
    const float* y0         = (const float*)d_in[2];
    const int*   turb_idx   = (const int*)d_in[3];
    const float* init_noise = (const float*)d_in[5];
    const float* turb_emb   = (const float*)d_in[6];
    const float* W_ih0      = (const float*)d_in[7];
    const float* W_hh0      = (const float*)d_in[8];
    const float* b_ih0      = (const float*)d_in[9];
    const float* b_hh0      = (const float*)d_in[10];
    const float* W_ih1      = (const float*)d_in[11];
    const float* W_hh1      = (const float*)d_in[12];
    const float* b_ih1      = (const float*)d_in[13];
    const float* b_hh1      = (const float*)d_in[14];
    const float* W1         = (const float*)d_in[15];
    const float* b1m        = (const float*)d_in[16];
    const float* W2         = (const float*)d_in[17];
    const float* b2m        = (const float*)d_in[18];
    const float* W3         = (const float*)d_in[19];
    const float* b3         = (const float*)d_in[20];
    float* out = (float*)d_out;

    prologue_kernel<<<128, 256>>>(W_ih0, W_hh0, b_ih0, b_hh0,
                                  W_ih1, W_hh1, b_ih1, b_hh1, W1, W2);

    cudaFuncSetAttribute(fused_kernel, cudaFuncAttributeMaxDynamicSharedMemorySize, SMEM_BYTES);
    fused_kernel<<<NBLK, NT, SMEM_BYTES>>>(x_hist, x_future, y0, turb_idx, init_noise,
                                           turb_emb, b1m, b2m, W3, b3, out);
}